// round 15
// baseline (speedup 1.0000x reference)
#include <cuda_runtime.h>
#include <cstddef>

// Problem constants
#define B_ 2
#define L_ 1024
#define D_ 128
#define V_ 5

// ---------------------------------------------------------------------------
// CONVERGED configuration + unroll-gradient probe.
// R14 (unroll 8): 152.35us wall (best), 151.0us ncu, 84.8% DRAM, issue 9.7%.
// This round: store-loop unroll 8 -> 16 (same gradient, regs 32 with 16
// headroom to the 48-reg/8CTA bound); everything else frozen at the
// best-measured optimum.
//
// Algebraic collapse: x has only V=5 values, so the whole einsum reduces to
// two 5x128 tables built per-block:
//   A[v][e]  = dot(emb[v], W[e][0:128]) + bias[e]
//   P2[v][e] = dot(emb[v], W[e][128:256])
//   m[b][e][l1][l2] = A[x[b][l1]][e] + P2[x[b][l2]][e]     (1 GiB pure stream)
//   s[b][l][d]      = emb[x[b][l]][d]                      (1 MiB, fused tail)
//
// grid = B*D*16 = 4096 blocks (slab-major); each block: one (b,e), 64-row l1
// chunk = 256 KiB contiguous, 256-bit streaming stores (st.global.cs.v8.f32).
//
// Axes closed with direct measurement (R2-R14): table-build fusion (-100us),
// s fusion (-6.5us) + tail position, grain size, store width/hints,
// occupancy/block shape, stream count, CTA->address mapping, gather
// placement, unroll depth (4->8 won ~1us).
// ---------------------------------------------------------------------------
__global__ __launch_bounds__(256, 8)
void fused_kernel(const int* __restrict__ x,
                  const float* __restrict__ emb,
                  const float* __restrict__ W,
                  const float* __restrict__ bias,
                  float4* __restrict__ out_s,
                  float4* __restrict__ out_m) {
    int slab  = blockIdx.x >> 4;   // 0..255  -> (b,e)
    int chunk = blockIdx.x & 15;   // l1 chunk of 64 rows
    int b = slab >> 7;
    int e = slab & 127;

    __shared__ float4 pv2[L_ / 4];   // 1024 floats: P2[x[b][l2]][e]
    __shared__ float  pc1[64];       // A[x[b][l1]][e] for this chunk
    __shared__ float  a5[V_], p5[V_];

    int tid  = threadIdx.x;
    int wid  = tid >> 5;
    int lane = tid & 31;

    // Warps 0..4: table build. Warp v computes both dot products for vocab
    // entry v against W row e (lane-strided, coalesced, L2-hot).
    if (wid < V_) {
        const float* w1 = W + (size_t)e * (2 * D_);
        const float* ev = emb + wid * D_;
        float s1 = 0.f, s2 = 0.f;
        #pragma unroll
        for (int d = lane; d < D_; d += 32) {
            float xv = ev[d];
            s1 += xv * w1[d];
            s2 += xv * w1[D_ + d];
        }
        #pragma unroll
        for (int o = 16; o; o >>= 1) {
            s1 += __shfl_xor_sync(0xFFFFFFFFu, s1, o);
            s2 += __shfl_xor_sync(0xFFFFFFFFu, s2, o);
        }
        if (lane == 0) {
            a5[wid] = s1 + bias[e];
            p5[wid] = s2;
        }
    }
    __syncthreads();

    // Build row/col vectors straight from global x (4 KiB, L2-hot).
    const int* xb = x + b * L_;
    int l1base = chunk * 64;
    float* pv2f = reinterpret_cast<float*>(pv2);
    #pragma unroll
    for (int l2 = tid; l2 < L_; l2 += 256) pv2f[l2] = p5[xb[l2]];
    if (tid < 64) pc1[tid] = a5[xb[l1base + tid]];
    __syncthreads();

    // Each thread owns a fixed 8-float column group (qp = tid & 127 is
    // loop-invariant): hoist the column vector; only the row constant varies.
    int qp = tid & 127;
    float4 b0 = pv2[2 * qp];
    float4 b1 = pv2[2 * qp + 1];

    // Streaming store: 64 rows x 128 groups = 8192 v8-stores / 256 thr
    // = 32 iters; 32B per lane -> 1 KiB contiguous per warp per instr.
    float* outf = reinterpret_cast<float*>(
        out_m + ((size_t)slab * L_ + l1base) * (L_ / 4));
    #pragma unroll 16
    for (int idx = tid; idx < 64 * 128; idx += 256) {
        int r = idx >> 7;        // row within chunk (warp-uniform)
        float c = pc1[r];
        float4 v0 = b0, v1 = b1;
        v0.x += c; v0.y += c; v0.z += c; v0.w += c;
        v1.x += c; v1.y += c; v1.z += c; v1.w += c;
        float* p = outf + (size_t)idx * 8;
        asm volatile(
            "st.global.cs.v8.f32 [%0], {%1,%2,%3,%4,%5,%6,%7,%8};"
            :: "l"(p),
               "f"(v0.x), "f"(v0.y), "f"(v0.z), "f"(v0.w),
               "f"(v1.x), "f"(v1.y), "f"(v1.z), "f"(v1.w)
            : "memory");
    }

    // Fused s slice in the tail (measured best position): 65536 float4 total
    // / 4096 blocks = 16 per block (half of warp 0; emb rows L2-resident).
    if (tid < 16) {
        int idx = blockIdx.x * 16 + tid;             // < 65536
        int row = idx >> 5;                          // (b*L + l), global
        int d4  = idx & 31;
        int v = x[row];
        out_s[idx] = reinterpret_cast<const float4*>(emb)[v * (D_ / 4) + d4];
    }
}

// ---------------------------------------------------------------------------
// kernel_launch
// inputs (metadata order): x(int32, B*L), emb_table(f32, V*D),
//                          W(f32, D*2D), b(f32, D)
// output: concat(s, m) as f32: s = B*L*D, m = B*D*L*L
// ---------------------------------------------------------------------------
extern "C" void kernel_launch(void* const* d_in, const int* in_sizes, int n_in,
                              void* d_out, int out_size) {
    const int*   x    = (const int*)d_in[0];
    const float* emb  = (const float*)d_in[1];
    const float* W    = (const float*)d_in[2];
    const float* bias = (const float*)d_in[3];

    float* out_s = (float*)d_out;
    float* out_m = out_s + (size_t)B_ * L_ * D_;

    fused_kernel<<<B_ * D_ * 16, 256>>>(x, emb, W, bias,
                                        (float4*)out_s, (float4*)out_m);
}

// round 16
// speedup vs baseline: 1.0029x; 1.0029x over previous
#include <cuda_runtime.h>
#include <cstddef>

// Problem constants
#define B_ 2
#define L_ 1024
#define D_ 128
#define V_ 5

// ---------------------------------------------------------------------------
// FINAL — exact R14 configuration, the session's best-measured kernel:
//   152.35us wall / 151.0us ncu / 84.8% DRAM ~= 6.72 TB/s effective write
//   = measured sm_103a pure-store roofline (residual = refresh/turnaround).
//
// Algebraic collapse: x has only V=5 values, so the whole einsum reduces to
// two 5x128 tables built per-block:
//   A[v][e]  = dot(emb[v], W[e][0:128]) + bias[e]
//   P2[v][e] = dot(emb[v], W[e][128:256])
//   m[b][e][l1][l2] = A[x[b][l1]][e] + P2[x[b][l2]][e]     (1 GiB pure stream)
//   s[b][l][d]      = emb[x[b][l]][d]                      (1 MiB, fused tail)
//
// grid = B*D*16 = 4096 blocks (slab-major); each block: one (b,e), 64-row l1
// chunk = 256 KiB contiguous, 256-bit streaming stores (st.global.cs.v8.f32,
// 1 KiB per warp per instruction), store loop unrolled 8x (measured optimum
// on the 4/8/16 curve: 153.4 / 152.35 / 152.58 us).
//
// All axes closed by direct measurement (R2-R15): table-build fusion
// (-100us), s fusion (-6.5us) + tail position, grain size (64-row;
// wave-aligned coarse regressed), store width v8 + .cs, occupancy/block
// shape, concurrent stream count, CTA->address mapping, gather placement,
// unroll depth. Four distinct structures pin at ~151 ncu-us => fabric
// ceiling; this source is the measured minimum.
// ---------------------------------------------------------------------------
__global__ __launch_bounds__(256, 8)
void fused_kernel(const int* __restrict__ x,
                  const float* __restrict__ emb,
                  const float* __restrict__ W,
                  const float* __restrict__ bias,
                  float4* __restrict__ out_s,
                  float4* __restrict__ out_m) {
    int slab  = blockIdx.x >> 4;   // 0..255  -> (b,e)
    int chunk = blockIdx.x & 15;   // l1 chunk of 64 rows
    int b = slab >> 7;
    int e = slab & 127;

    __shared__ float4 pv2[L_ / 4];   // 1024 floats: P2[x[b][l2]][e]
    __shared__ float  pc1[64];       // A[x[b][l1]][e] for this chunk
    __shared__ float  a5[V_], p5[V_];

    int tid  = threadIdx.x;
    int wid  = tid >> 5;
    int lane = tid & 31;

    // Warps 0..4: table build. Warp v computes both dot products for vocab
    // entry v against W row e (lane-strided, coalesced, L2-hot).
    if (wid < V_) {
        const float* w1 = W + (size_t)e * (2 * D_);
        const float* ev = emb + wid * D_;
        float s1 = 0.f, s2 = 0.f;
        #pragma unroll
        for (int d = lane; d < D_; d += 32) {
            float xv = ev[d];
            s1 += xv * w1[d];
            s2 += xv * w1[D_ + d];
        }
        #pragma unroll
        for (int o = 16; o; o >>= 1) {
            s1 += __shfl_xor_sync(0xFFFFFFFFu, s1, o);
            s2 += __shfl_xor_sync(0xFFFFFFFFu, s2, o);
        }
        if (lane == 0) {
            a5[wid] = s1 + bias[e];
            p5[wid] = s2;
        }
    }
    __syncthreads();

    // Build row/col vectors straight from global x (4 KiB, L2-hot).
    const int* xb = x + b * L_;
    int l1base = chunk * 64;
    float* pv2f = reinterpret_cast<float*>(pv2);
    #pragma unroll
    for (int l2 = tid; l2 < L_; l2 += 256) pv2f[l2] = p5[xb[l2]];
    if (tid < 64) pc1[tid] = a5[xb[l1base + tid]];
    __syncthreads();

    // Each thread owns a fixed 8-float column group (qp = tid & 127 is
    // loop-invariant): hoist the column vector; only the row constant varies.
    int qp = tid & 127;
    float4 b0 = pv2[2 * qp];
    float4 b1 = pv2[2 * qp + 1];

    // Streaming store: 64 rows x 128 groups = 8192 v8-stores / 256 thr
    // = 32 iters; 32B per lane -> 1 KiB contiguous per warp per instr.
    float* outf = reinterpret_cast<float*>(
        out_m + ((size_t)slab * L_ + l1base) * (L_ / 4));
    #pragma unroll 8
    for (int idx = tid; idx < 64 * 128; idx += 256) {
        int r = idx >> 7;        // row within chunk (warp-uniform)
        float c = pc1[r];
        float4 v0 = b0, v1 = b1;
        v0.x += c; v0.y += c; v0.z += c; v0.w += c;
        v1.x += c; v1.y += c; v1.z += c; v1.w += c;
        float* p = outf + (size_t)idx * 8;
        asm volatile(
            "st.global.cs.v8.f32 [%0], {%1,%2,%3,%4,%5,%6,%7,%8};"
            :: "l"(p),
               "f"(v0.x), "f"(v0.y), "f"(v0.z), "f"(v0.w),
               "f"(v1.x), "f"(v1.y), "f"(v1.z), "f"(v1.w)
            : "memory");
    }

    // Fused s slice in the tail (measured best position): 65536 float4 total
    // / 4096 blocks = 16 per block (half of warp 0; emb rows L2-resident).
    if (tid < 16) {
        int idx = blockIdx.x * 16 + tid;             // < 65536
        int row = idx >> 5;                          // (b*L + l), global
        int d4  = idx & 31;
        int v = x[row];
        out_s[idx] = reinterpret_cast<const float4*>(emb)[v * (D_ / 4) + d4];
    }
}

// ---------------------------------------------------------------------------
// kernel_launch
// inputs (metadata order): x(int32, B*L), emb_table(f32, V*D),
//                          W(f32, D*2D), b(f32, D)
// output: concat(s, m) as f32: s = B*L*D, m = B*D*L*L
// ---------------------------------------------------------------------------
extern "C" void kernel_launch(void* const* d_in, const int* in_sizes, int n_in,
                              void* d_out, int out_size) {
    const int*   x    = (const int*)d_in[0];
    const float* emb  = (const float*)d_in[1];
    const float* W    = (const float*)d_in[2];
    const float* bias = (const float*)d_in[3];

    float* out_s = (float*)d_out;
    float* out_m = out_s + (size_t)B_ * L_ * D_;

    fused_kernel<<<B_ * D_ * 16, 256>>>(x, emb, W, bias,
                                        (float4*)out_s, (float4*)out_m);
}

// round 17
// speedup vs baseline: 1.0034x; 1.0004x over previous
#include <cuda_runtime.h>
#include <cstddef>

// Problem constants
#define B_ 2
#define L_ 1024
#define D_ 128
#define V_ 5

// ---------------------------------------------------------------------------
// FINAL (converged, 3x reproduced): 152.1-152.4us wall, 150.3-151.0us ncu,
// 84.8-85.2% DRAM ~= 6.76 TB/s effective write = measured sm_103a pure-store
// roofline (residual = DRAM refresh/bank turnaround; not kernel-addressable).
//
// Algebraic collapse: x has only V=5 values, so the whole einsum reduces to
// two 5x128 tables built per-block:
//   A[v][e]  = dot(emb[v], W[e][0:128]) + bias[e]
//   P2[v][e] = dot(emb[v], W[e][128:256])
//   m[b][e][l1][l2] = A[x[b][l1]][e] + P2[x[b][l2]][e]     (1 GiB pure stream)
//   s[b][l][d]      = emb[x[b][l]][d]                      (1 MiB, fused tail)
//
// grid = B*D*16 = 4096 blocks (slab-major); each block: one (b,e), 64-row l1
// chunk = 256 KiB contiguous, 256-bit streaming stores (st.global.cs.v8.f32,
// 1 KiB per warp per instruction), store loop unrolled 8x (measured optimum
// on the 4/8/16 curve: 153.4 / 152.35 / 152.58 us).
//
// All axes closed by direct measurement (R2-R16): table-build fusion
// (-100us), s fusion (-6.5us) + tail position, grain size (64-row;
// wave-aligned coarse regressed -16us), store width v8 + .cs, occupancy /
// block shape, concurrent stream count, CTA->address mapping, gather
// placement, unroll depth. Four structurally distinct kernels pin at the
// same ~151 ncu-us fabric ceiling; this source is the measured minimum.
// ---------------------------------------------------------------------------
__global__ __launch_bounds__(256, 8)
void fused_kernel(const int* __restrict__ x,
                  const float* __restrict__ emb,
                  const float* __restrict__ W,
                  const float* __restrict__ bias,
                  float4* __restrict__ out_s,
                  float4* __restrict__ out_m) {
    int slab  = blockIdx.x >> 4;   // 0..255  -> (b,e)
    int chunk = blockIdx.x & 15;   // l1 chunk of 64 rows
    int b = slab >> 7;
    int e = slab & 127;

    __shared__ float4 pv2[L_ / 4];   // 1024 floats: P2[x[b][l2]][e]
    __shared__ float  pc1[64];       // A[x[b][l1]][e] for this chunk
    __shared__ float  a5[V_], p5[V_];

    int tid  = threadIdx.x;
    int wid  = tid >> 5;
    int lane = tid & 31;

    // Warps 0..4: table build. Warp v computes both dot products for vocab
    // entry v against W row e (lane-strided, coalesced, L2-hot).
    if (wid < V_) {
        const float* w1 = W + (size_t)e * (2 * D_);
        const float* ev = emb + wid * D_;
        float s1 = 0.f, s2 = 0.f;
        #pragma unroll
        for (int d = lane; d < D_; d += 32) {
            float xv = ev[d];
            s1 += xv * w1[d];
            s2 += xv * w1[D_ + d];
        }
        #pragma unroll
        for (int o = 16; o; o >>= 1) {
            s1 += __shfl_xor_sync(0xFFFFFFFFu, s1, o);
            s2 += __shfl_xor_sync(0xFFFFFFFFu, s2, o);
        }
        if (lane == 0) {
            a5[wid] = s1 + bias[e];
            p5[wid] = s2;
        }
    }
    __syncthreads();

    // Build row/col vectors straight from global x (4 KiB, L2-hot).
    const int* xb = x + b * L_;
    int l1base = chunk * 64;
    float* pv2f = reinterpret_cast<float*>(pv2);
    #pragma unroll
    for (int l2 = tid; l2 < L_; l2 += 256) pv2f[l2] = p5[xb[l2]];
    if (tid < 64) pc1[tid] = a5[xb[l1base + tid]];
    __syncthreads();

    // Each thread owns a fixed 8-float column group (qp = tid & 127 is
    // loop-invariant): hoist the column vector; only the row constant varies.
    int qp = tid & 127;
    float4 b0 = pv2[2 * qp];
    float4 b1 = pv2[2 * qp + 1];

    // Streaming store: 64 rows x 128 groups = 8192 v8-stores / 256 thr
    // = 32 iters; 32B per lane -> 1 KiB contiguous per warp per instr.
    float* outf = reinterpret_cast<float*>(
        out_m + ((size_t)slab * L_ + l1base) * (L_ / 4));
    #pragma unroll 8
    for (int idx = tid; idx < 64 * 128; idx += 256) {
        int r = idx >> 7;        // row within chunk (warp-uniform)
        float c = pc1[r];
        float4 v0 = b0, v1 = b1;
        v0.x += c; v0.y += c; v0.z += c; v0.w += c;
        v1.x += c; v1.y += c; v1.z += c; v1.w += c;
        float* p = outf + (size_t)idx * 8;
        asm volatile(
            "st.global.cs.v8.f32 [%0], {%1,%2,%3,%4,%5,%6,%7,%8};"
            :: "l"(p),
               "f"(v0.x), "f"(v0.y), "f"(v0.z), "f"(v0.w),
               "f"(v1.x), "f"(v1.y), "f"(v1.z), "f"(v1.w)
            : "memory");
    }

    // Fused s slice in the tail (measured best position): 65536 float4 total
    // / 4096 blocks = 16 per block (half of warp 0; emb rows L2-resident).
    if (tid < 16) {
        int idx = blockIdx.x * 16 + tid;             // < 65536
        int row = idx >> 5;                          // (b*L + l), global
        int d4  = idx & 31;
        int v = x[row];
        out_s[idx] = reinterpret_cast<const float4*>(emb)[v * (D_ / 4) + d4];
    }
}

// ---------------------------------------------------------------------------
// kernel_launch
// inputs (metadata order): x(int32, B*L), emb_table(f32, V*D),
//                          W(f32, D*2D), b(f32, D)
// output: concat(s, m) as f32: s = B*L*D, m = B*D*L*L
// ---------------------------------------------------------------------------
extern "C" void kernel_launch(void* const* d_in, const int* in_sizes, int n_in,
                              void* d_out, int out_size) {
    const int*   x    = (const int*)d_in[0];
    const float* emb  = (const float*)d_in[1];
    const float* W    = (const float*)d_in[2];
    const float* bias = (const float*)d_in[3];

    float* out_s = (float*)d_out;
    float* out_m = out_s + (size_t)B_ * L_ * D_;

    fused_kernel<<<B_ * D_ * 16, 256>>>(x, emb, W, bias,
                                        (float4*)out_s, (float4*)out_m);
}